// round 1
// baseline (speedup 1.0000x reference)
#include <cuda_runtime.h>
#include <math.h>
#include <stdint.h>

#define NA 50000
#define GD 15
#define NC (GD*GD*GD)
#define MP 2000000

// ---------------- scratch (no allocs allowed) ----------------
__device__ int   g_flat[NA];
__device__ int   g_cnt[NC];
__device__ int   g_start[NC];
__device__ int   g_fill[NC];
__device__ int   g_sorted[NA];          // atom ids in image (sorted) order
__device__ float g_sxv[NA], g_syv[NA], g_szv[NA];  // coords in image order
__device__ int   g_akept[NA];
__device__ int   g_aoff[NA];
__device__ int   g_wkept[NC];
__device__ int   g_woff[NC];
__device__ int   g_totalS;

__constant__ int c_off[13][3] = {
  {-1,0,0},{-1,-1,0},{0,-1,0},{1,-1,0},{-1,1,-1},{0,1,-1},{1,1,-1},
  {-1,0,-1},{0,0,-1},{1,0,-1},{-1,-1,-1},{0,-1,-1},{1,-1,-1}};

// ---------------- kernels ----------------
__global__ void k_zero() {
  int i = blockIdx.x*blockDim.x + threadIdx.x;
  if (i < NC) { g_cnt[i] = 0; g_fill[i] = 0; }
}

__device__ __forceinline__ int cellcoord(double v) {
  // replicate: frac = coords@inv(cell); frac -= floor(frac); wrap; idx = floor(frac*G)
  const double inv = 1.0/80.0;
  double f = __dmul_rn(v, inv);
  f = f - floor(f);
  if (f >= 1.0) f -= 1.0;
  if (f <  0.0) f += 1.0;
  return (int)floor(__dmul_rn(f, (double)GD));
}

__global__ void k_assign(const float* __restrict__ coords) {
  int i = blockIdx.x*blockDim.x + threadIdx.x;
  if (i >= NA) return;
  int x = cellcoord((double)coords[3*i+0]);
  int y = cellcoord((double)coords[3*i+1]);
  int z = cellcoord((double)coords[3*i+2]);
  int f = (x*GD + y)*GD + z;
  g_flat[i] = f;
  atomicAdd(&g_cnt[f], 1);
}

// single-block exclusive scan; mode 0: cnt->start, 1: akept->aoff (total->g_totalS),
// 2: wkept->woff with base g_totalS
__global__ void k_scan(int mode) {
  const int* in; int* out; int n;
  if (mode == 0)      { in = g_cnt;   out = g_start; n = NC; }
  else if (mode == 1) { in = g_akept; out = g_aoff;  n = NA; }
  else                { in = g_wkept; out = g_woff;  n = NC; }
  __shared__ int wsum[32];
  __shared__ int carry;
  int lane = threadIdx.x & 31, wid = threadIdx.x >> 5;
  int nw = blockDim.x >> 5;
  if (threadIdx.x == 0) carry = (mode == 2) ? g_totalS : 0;
  __syncthreads();
  for (int s0 = 0; s0 < n; s0 += blockDim.x) {
    int i = s0 + threadIdx.x;
    int v = (i < n) ? in[i] : 0;
    int x = v;
    #pragma unroll
    for (int o = 1; o < 32; o <<= 1) {
      int y = __shfl_up_sync(0xffffffffu, x, o);
      if (lane >= o) x += y;
    }
    if (lane == 31) wsum[wid] = x;
    __syncthreads();
    if (wid == 0) {
      int w = (lane < nw) ? wsum[lane] : 0;
      #pragma unroll
      for (int o = 1; o < 32; o <<= 1) {
        int y = __shfl_up_sync(0xffffffffu, w, o);
        if (lane >= o) w += y;
      }
      wsum[lane] = w;
    }
    __syncthreads();
    int bp  = wid ? wsum[wid-1] : 0;
    int tot = wsum[nw-1];
    if (i < n) out[i] = carry + bp + x - v;
    __syncthreads();
    if (threadIdx.x == 0) carry += tot;
    __syncthreads();
  }
  if (threadIdx.x == 0 && mode == 1) g_totalS = carry;
}

__global__ void k_scatter() {
  int i = blockIdx.x*blockDim.x + threadIdx.x;
  if (i >= NA) return;
  int f = g_flat[i];
  int slot = atomicAdd(&g_fill[f], 1);
  g_sorted[g_start[f] + slot] = i;
}

// stable order = sort each cell's atoms ascending by id; also build sorted coord arrays
__global__ void k_sortcell(const float* __restrict__ coords) {
  int c = blockIdx.x*blockDim.x + threadIdx.x;
  if (c >= NC) return;
  int s = g_start[c], n = g_cnt[c];
  for (int i = 1; i < n; i++) {
    int v = g_sorted[s+i]; int j = i-1;
    while (j >= 0 && g_sorted[s+j] > v) { g_sorted[s+j+1] = g_sorted[s+j]; j--; }
    g_sorted[s+j+1] = v;
  }
  for (int k = 0; k < n; k++) {
    int a = g_sorted[s+k];
    g_sxv[s+k] = coords[3*a+0];
    g_syv[s+k] = coords[3*a+1];
    g_szv[s+k] = coords[3*a+2];
  }
}

// keep test: float fast path, exact float64 path near the boundary (matches numpy)
__device__ __forceinline__ bool keep_pair(float ax, float ay, float az,
                                          float bx, float by, float bz,
                                          int sx, int sy, int sz,
                                          float& dx, float& dy, float& dz) {
  float fsx = (float)sx * 80.0f, fsy = (float)sy * 80.0f, fsz = (float)sz * 80.0f;
  dx = (ax - bx) + fsx;
  dy = (ay - by) + fsy;
  dz = (az - bz) + fsz;
  float sq = dx*dx + dy*dy + dz*dz;
  if (sq <= 27.0290f) return true;     // (5.2 - 1e-3)^2 = 27.029601
  if (sq >  27.0510f) return false;    // (5.2 + 1e-3)^2 = 27.050401
  // exact path: replicate numpy float64 ops, no fma contraction
  double ddx = __dadd_rn(__dsub_rn((double)ax, (double)bx), (double)sx * 80.0);
  double ddy = __dadd_rn(__dsub_rn((double)ay, (double)by), (double)sy * 80.0);
  double ddz = __dadd_rn(__dsub_rn((double)az, (double)bz), (double)sz * 80.0);
  double dsq = __dadd_rn(__dadd_rn(__dmul_rn(ddx,ddx), __dmul_rn(ddy,ddy)), __dmul_rn(ddz,ddz));
  return sqrt(dsq) <= 5.2;
}

__device__ __forceinline__ void write_pair(float* __restrict__ out, int p,
                                           int a, int b, float dx, float dy, float dz) {
  out[p]        = (float)a;
  out[MP + p]   = (float)b;
  float sq = dx*dx + dy*dy + dz*dz;
  out[2*MP + p] = sqrtf(sq);
  out[3*MP + 3*p + 0] = dx;
  out[3*MP + 3*p + 1] = dy;
  out[3*MP + 3*p + 2] = dz;
  out[6*MP + p] = 1.0f;
}

// surround pairs: one warp per atom; order = atom asc -> offset 0..12 -> slot asc
// phase 0: count -> g_akept ; phase 1: write at g_aoff
__global__ void k_surround(const float* __restrict__ coords, int phase, float* __restrict__ out) {
  int w = (blockIdx.x*blockDim.x + threadIdx.x) >> 5;
  int lane = threadIdx.x & 31;
  if (w >= NA) return;
  int a = w;
  float ax = coords[3*a+0], ay = coords[3*a+1], az = coords[3*a+2];
  int f = g_flat[a];
  int cz = f % GD, cy = (f / GD) % GD, cx = f / (GD*GD);
  int wp = phase ? g_aoff[a] : 0;
  #pragma unroll 1
  for (int o = 0; o < 13; o++) {
    int nx = cx + c_off[o][0], ny = cy + c_off[o][1], nz = cz + c_off[o][2];
    int sx = 0, sy = 0, sz = 0;
    if (nx < 0) { nx += GD; sx = 1; } else if (nx >= GD) { nx -= GD; sx = -1; }
    if (ny < 0) { ny += GD; sy = 1; } else if (ny >= GD) { ny -= GD; sy = -1; }
    if (nz < 0) { nz += GD; sz = 1; } else if (nz >= GD) { nz -= GD; sz = -1; }
    int nc = (nx*GD + ny)*GD + nz;
    int s = g_start[nc], c = g_cnt[nc];
    for (int k0 = 0; k0 < c; k0 += 32) {
      int k = k0 + lane;
      bool kp = false; int b = 0; float dx = 0.f, dy = 0.f, dz = 0.f;
      if (k < c) {
        int j = s + k;
        float bx = g_sxv[j], by = g_syv[j], bz = g_szv[j];
        kp = keep_pair(ax, ay, az, bx, by, bz, sx, sy, sz, dx, dy, dz);
        if (kp) b = g_sorted[j];
      }
      unsigned m = __ballot_sync(0xffffffffu, kp);
      if (phase && kp) {
        int p = wp + __popc(m & ((1u << lane) - 1u));
        write_pair(out, p, a, b, dx, dy, dz);
      }
      wp += __popc(m);
    }
  }
  if (!phase && lane == 0) g_akept[a] = wp;
}

// within-cell pairs: one warp per cell; order = cell asc -> tril (i asc, j asc, i>j)
__global__ void k_within(int phase, float* __restrict__ out) {
  int w = (blockIdx.x*blockDim.x + threadIdx.x) >> 5;
  int lane = threadIdx.x & 31;
  if (w >= NC) return;
  int s = g_start[w], c = g_cnt[w];
  int T = c*(c-1)/2;
  int wp = phase ? g_woff[w] : 0;
  for (int t0 = 0; t0 < T; t0 += 32) {
    int t = t0 + lane;
    bool kp = false; int aa = 0, bb = 0; float dx = 0.f, dy = 0.f, dz = 0.f;
    if (t < T) {
      int i = (int)((1.0f + sqrtf(8.0f*(float)t + 1.0f)) * 0.5f);
      while (i*(i-1)/2 > t) i--;
      while ((i+1)*i/2 <= t) i++;
      int j = t - i*(i-1)/2;
      int ja = s + i, jb = s + j;
      float ax = g_sxv[ja], ay = g_syv[ja], az = g_szv[ja];
      float bx = g_sxv[jb], by = g_syv[jb], bz = g_szv[jb];
      kp = keep_pair(ax, ay, az, bx, by, bz, 0, 0, 0, dx, dy, dz);
      if (kp) { aa = g_sorted[ja]; bb = g_sorted[jb]; }
    }
    unsigned m = __ballot_sync(0xffffffffu, kp);
    if (phase && kp) {
      int p = wp + __popc(m & ((1u << lane) - 1u));
      write_pair(out, p, aa, bb, dx, dy, dz);
    }
    wp += __popc(m);
  }
  if (!phase && lane == 0) g_wkept[w] = wp;
}

// ---------------- launch ----------------
extern "C" void kernel_launch(void* const* d_in, const int* in_sizes, int n_in,
                              void* d_out, int out_size) {
  // locate coords by size (3*NA); robust to metadata ordering
  const float* coords = nullptr;
  for (int i = 0; i < n_in; i++)
    if (in_sizes[i] == 3*NA) coords = (const float*)d_in[i];
  float* out = (float*)d_out;

  cudaMemsetAsync(d_out, 0, (size_t)out_size * sizeof(float));
  k_zero<<<(NC + 255)/256, 256>>>();
  k_assign<<<(NA + 255)/256, 256>>>(coords);
  k_scan<<<1, 1024>>>(0);                               // cnt -> start
  k_scatter<<<(NA + 255)/256, 256>>>();
  k_sortcell<<<(NC + 127)/128, 128>>>(coords);
  k_surround<<<(NA*32 + 255)/256, 256>>>(coords, 0, nullptr);  // count
  k_scan<<<1, 1024>>>(1);                               // akept -> aoff, total
  k_within<<<(NC*32 + 255)/256, 256>>>(0, nullptr);     // count
  k_scan<<<1, 1024>>>(2);                               // wkept -> woff (+base)
  k_surround<<<(NA*32 + 255)/256, 256>>>(coords, 1, out);
  k_within<<<(NC*32 + 255)/256, 256>>>(1, out);
}

// round 2
// speedup vs baseline: 3.3126x; 3.3126x over previous
#include <cuda_runtime.h>
#include <math.h>
#include <stdint.h>

#define NA 50000
#define GD 15
#define NC (GD*GD*GD)
#define MP 2000000
#define CAP_A 96
#define CAP_W 768

// ---------------- scratch (no allocs allowed) ----------------
__device__ int    g_flat[NA];
__device__ int    g_cnt[NC];
__device__ int    g_start[NC];
__device__ int    g_fill[NC];
__device__ int    g_sorted[NA];          // atom ids in image (sorted) order
__device__ float  g_sxv[NA], g_syv[NA], g_szv[NA];  // coords in image order
__device__ int    g_akept[NA];
__device__ int    g_aoff[NA];
__device__ int    g_wkept[NC];
__device__ int    g_woff[NC];
__device__ int    g_totalS;
__device__ int    g_totalAll;
__device__ float4 g_scrA[(size_t)NA * CAP_A];   // per-atom surround staging (76.8MB)
__device__ float4 g_scrW[(size_t)NC * CAP_W];   // per-cell within staging (41.5MB)

__constant__ int c_off[13][3] = {
  {-1,0,0},{-1,-1,0},{0,-1,0},{1,-1,0},{-1,1,-1},{0,1,-1},{1,1,-1},
  {-1,0,-1},{0,0,-1},{1,0,-1},{-1,-1,-1},{0,-1,-1},{1,-1,-1}};

// ---------------- kernels ----------------
__global__ void k_zero() {
  int i = blockIdx.x*blockDim.x + threadIdx.x;
  if (i < NC) { g_cnt[i] = 0; g_fill[i] = 0; }
}

__device__ __forceinline__ int cellcoord(double v) {
  const double inv = 1.0/80.0;
  double f = __dmul_rn(v, inv);
  f = f - floor(f);
  if (f >= 1.0) f -= 1.0;
  if (f <  0.0) f += 1.0;
  return (int)floor(__dmul_rn(f, (double)GD));
}

__global__ void k_assign(const float* __restrict__ coords) {
  int i = blockIdx.x*blockDim.x + threadIdx.x;
  if (i >= NA) return;
  int x = cellcoord((double)coords[3*i+0]);
  int y = cellcoord((double)coords[3*i+1]);
  int z = cellcoord((double)coords[3*i+2]);
  int f = (x*GD + y)*GD + z;
  g_flat[i] = f;
  atomicAdd(&g_cnt[f], 1);
}

// single-block exclusive scan; mode 0: cnt->start, 1: akept->aoff (total->g_totalS),
// 2: wkept->woff with base g_totalS (grand total -> g_totalAll)
__global__ void k_scan(int mode) {
  const int* in; int* out; int n;
  if (mode == 0)      { in = g_cnt;   out = g_start; n = NC; }
  else if (mode == 1) { in = g_akept; out = g_aoff;  n = NA; }
  else                { in = g_wkept; out = g_woff;  n = NC; }
  __shared__ int wsum[32];
  __shared__ int carry;
  int lane = threadIdx.x & 31, wid = threadIdx.x >> 5;
  int nw = blockDim.x >> 5;
  if (threadIdx.x == 0) carry = (mode == 2) ? g_totalS : 0;
  __syncthreads();
  for (int s0 = 0; s0 < n; s0 += blockDim.x) {
    int i = s0 + threadIdx.x;
    int v = (i < n) ? in[i] : 0;
    int x = v;
    #pragma unroll
    for (int o = 1; o < 32; o <<= 1) {
      int y = __shfl_up_sync(0xffffffffu, x, o);
      if (lane >= o) x += y;
    }
    if (lane == 31) wsum[wid] = x;
    __syncthreads();
    if (wid == 0) {
      int w = (lane < nw) ? wsum[lane] : 0;
      #pragma unroll
      for (int o = 1; o < 32; o <<= 1) {
        int y = __shfl_up_sync(0xffffffffu, w, o);
        if (lane >= o) w += y;
      }
      wsum[lane] = w;
    }
    __syncthreads();
    int bp  = wid ? wsum[wid-1] : 0;
    int tot = wsum[nw-1];
    if (i < n) out[i] = carry + bp + x - v;
    __syncthreads();
    if (threadIdx.x == 0) carry += tot;
    __syncthreads();
  }
  if (threadIdx.x == 0) {
    if (mode == 1) g_totalS  = carry;
    if (mode == 2) g_totalAll = carry;
  }
}

__global__ void k_scatter() {
  int i = blockIdx.x*blockDim.x + threadIdx.x;
  if (i >= NA) return;
  int f = g_flat[i];
  int slot = atomicAdd(&g_fill[f], 1);
  g_sorted[g_start[f] + slot] = i;
}

// stable order = sort each cell's atoms ascending by id; also build sorted coord arrays
__global__ void k_sortcell(const float* __restrict__ coords) {
  int c = blockIdx.x*blockDim.x + threadIdx.x;
  if (c >= NC) return;
  int s = g_start[c], n = g_cnt[c];
  for (int i = 1; i < n; i++) {
    int v = g_sorted[s+i]; int j = i-1;
    while (j >= 0 && g_sorted[s+j] > v) { g_sorted[s+j+1] = g_sorted[s+j]; j--; }
    g_sorted[s+j+1] = v;
  }
  for (int k = 0; k < n; k++) {
    int a = g_sorted[s+k];
    g_sxv[s+k] = coords[3*a+0];
    g_syv[s+k] = coords[3*a+1];
    g_szv[s+k] = coords[3*a+2];
  }
}

// keep test: float fast path, exact float64 path near the boundary (matches numpy)
__device__ __forceinline__ bool keep_pair(float ax, float ay, float az,
                                          float bx, float by, float bz,
                                          float fsx, float fsy, float fsz,
                                          float& dx, float& dy, float& dz) {
  dx = (ax - bx) + fsx;
  dy = (ay - by) + fsy;
  dz = (az - bz) + fsz;
  float sq = dx*dx + dy*dy + dz*dz;
  if (sq <= 27.0290f) return true;     // (5.2 - 1e-3)^2
  if (sq >  27.0510f) return false;    // (5.2 + 1e-3)^2
  double ddx = __dadd_rn(__dsub_rn((double)ax, (double)bx), (double)fsx);
  double ddy = __dadd_rn(__dsub_rn((double)ay, (double)by), (double)fsy);
  double ddz = __dadd_rn(__dsub_rn((double)az, (double)bz), (double)fsz);
  double dsq = __dadd_rn(__dadd_rn(__dmul_rn(ddx,ddx), __dmul_rn(ddy,ddy)), __dmul_rn(ddz,ddz));
  return sqrt(dsq) <= 5.2;
}

// surround pairs, single pass: flattened 13-segment iteration, one warp per atom.
// order = atom asc -> offset 0..12 -> slot asc. Kept pairs staged in g_scrA.
__global__ void __launch_bounds__(256) k_surround(const float* __restrict__ coords) {
  const unsigned FULL = 0xffffffffu;
  int w = (blockIdx.x*blockDim.x + threadIdx.x) >> 5;
  int lane = threadIdx.x & 31;
  int wl = (threadIdx.x >> 5);
  __shared__ int sh_base[8][13];   // segS - cumBefore
  __shared__ int sh_end [8][13];   // inclusive prefix of counts
  __shared__ int sh_shf [8][13];   // packed shift
  if (w >= NA) return;
  int a = w;
  float ax = coords[3*a+0], ay = coords[3*a+1], az = coords[3*a+2];
  int f = g_flat[a];
  int cz = f % GD, cy = (f / GD) % GD, cx = f / (GD*GD);

  int segC = 0, segS = 0, segSh = 0;
  if (lane < 13) {
    int nx = cx + c_off[lane][0], ny = cy + c_off[lane][1], nz = cz + c_off[lane][2];
    int sx = 0, sy = 0, sz = 0;
    if (nx < 0) { nx += GD; sx = 1; } else if (nx >= GD) { nx -= GD; sx = -1; }
    if (ny < 0) { ny += GD; sy = 1; } else if (ny >= GD) { ny -= GD; sy = -1; }
    if (nz < 0) { nz += GD; sz = 1; } else if (nz >= GD) { nz -= GD; sz = -1; }
    int nc = (nx*GD + ny)*GD + nz;
    segS = g_start[nc]; segC = g_cnt[nc];
    segSh = (sx+1) | ((sy+1)<<2) | ((sz+1)<<4);
  }
  // inclusive prefix of segC over lanes
  int pre = segC;
  #pragma unroll
  for (int o = 1; o < 16; o <<= 1) {
    int y = __shfl_up_sync(FULL, pre, o);
    if (lane >= o) pre += y;
  }
  int total = __shfl_sync(FULL, pre, 12);
  if (lane < 13) {
    sh_base[wl][lane] = segS - (pre - segC);
    sh_end [wl][lane] = pre;
    sh_shf [wl][lane] = segSh;
  }
  __syncwarp();

  float4* scr = &g_scrA[(size_t)a * CAP_A];
  int wp = 0;
  for (int t0 = 0; t0 < total; t0 += 32) {
    int t = t0 + lane;
    bool kp = false; int b = 0; float dx = 0.f, dy = 0.f, dz = 0.f;
    if (t < total) {
      int o = 0;
      #pragma unroll
      for (int q = 0; q < 13; q++) o += (t >= sh_end[wl][q]);
      int j   = sh_base[wl][o] + t;
      int shp = sh_shf[wl][o];
      float fsx = (float)((shp      & 3) - 1) * 80.0f;
      float fsy = (float)(((shp>>2) & 3) - 1) * 80.0f;
      float fsz = (float)(((shp>>4) & 3) - 1) * 80.0f;
      float bx = g_sxv[j], by = g_syv[j], bz = g_szv[j];
      kp = keep_pair(ax, ay, az, bx, by, bz, fsx, fsy, fsz, dx, dy, dz);
      if (kp) b = g_sorted[j];
    }
    unsigned m = __ballot_sync(FULL, kp);
    if (kp) {
      int p = wp + __popc(m & ((1u << lane) - 1u));
      scr[p] = make_float4(__int_as_float(b), dx, dy, dz);
    }
    wp += __popc(m);
  }
  if (lane == 0) g_akept[a] = wp;
}

// within-cell pairs, single pass: one warp per cell; tril order; staged in g_scrW
__global__ void __launch_bounds__(256) k_within() {
  const unsigned FULL = 0xffffffffu;
  int w = (blockIdx.x*blockDim.x + threadIdx.x) >> 5;
  int lane = threadIdx.x & 31;
  if (w >= NC) return;
  int s = g_start[w], c = g_cnt[w];
  int T = c*(c-1)/2;
  float4* scr = &g_scrW[(size_t)w * CAP_W];
  int wp = 0;
  for (int t0 = 0; t0 < T; t0 += 32) {
    int t = t0 + lane;
    bool kp = false; int ij = 0; float dx = 0.f, dy = 0.f, dz = 0.f;
    if (t < T) {
      int i = (int)((1.0f + sqrtf(8.0f*(float)t + 1.0f)) * 0.5f);
      while (i*(i-1)/2 > t) i--;
      while ((i+1)*i/2 <= t) i++;
      int j = t - i*(i-1)/2;
      int ja = s + i, jb = s + j;
      float axx = g_sxv[ja], ayy = g_syv[ja], azz = g_szv[ja];
      float bx  = g_sxv[jb], by  = g_syv[jb], bz  = g_szv[jb];
      kp = keep_pair(axx, ayy, azz, bx, by, bz, 0.f, 0.f, 0.f, dx, dy, dz);
      ij = i | (j << 8);
    }
    unsigned m = __ballot_sync(FULL, kp);
    if (kp) {
      int p = wp + __popc(m & ((1u << lane) - 1u));
      scr[p] = make_float4(__int_as_float(ij), dx, dy, dz);
    }
    wp += __popc(m);
  }
  if (lane == 0) g_wkept[w] = wp;
}

// zero only the padded tail [totalAll, MP) of every output column
__global__ void k_tail(float* __restrict__ out) {
  __shared__ int sh_total;
  if (threadIdx.x == 0) sh_total = g_totalAll;
  __syncthreads();
  int i = blockIdx.x*blockDim.x + threadIdx.x;
  if (i >= MP || i < sh_total) return;
  out[i]        = 0.f;
  out[MP + i]   = 0.f;
  out[2*MP + i] = 0.f;
  out[3*MP + 3*i + 0] = 0.f;
  out[3*MP + 3*i + 1] = 0.f;
  out[3*MP + 3*i + 2] = 0.f;
  out[6*MP + i] = 0.f;
}

__device__ __forceinline__ void emit_one(float* __restrict__ out, int p,
                                         float fa, float fb,
                                         float dx, float dy, float dz) {
  out[p]        = fa;
  out[MP + p]   = fb;
  out[2*MP + p] = sqrtf(dx*dx + dy*dy + dz*dz);
  out[3*MP + 3*p + 0] = dx;
  out[3*MP + 3*p + 1] = dy;
  out[3*MP + 3*p + 2] = dz;
  out[6*MP + p] = 1.0f;
}

__global__ void k_emitA(float* __restrict__ out) {
  int w = (blockIdx.x*blockDim.x + threadIdx.x) >> 5;
  int lane = threadIdx.x & 31;
  if (w >= NA) return;
  int n = g_akept[w], off = g_aoff[w];
  const float4* scr = &g_scrA[(size_t)w * CAP_A];
  float fa = (float)w;
  for (int k = lane; k < n; k += 32) {
    float4 v = scr[k];
    emit_one(out, off + k, fa, (float)__float_as_int(v.x), v.y, v.z, v.w);
  }
}

__global__ void k_emitW(float* __restrict__ out) {
  int w = (blockIdx.x*blockDim.x + threadIdx.x) >> 5;
  int lane = threadIdx.x & 31;
  if (w >= NC) return;
  int n = g_wkept[w], off = g_woff[w], s = g_start[w];
  const float4* scr = &g_scrW[(size_t)w * CAP_W];
  for (int k = lane; k < n; k += 32) {
    float4 v = scr[k];
    int ij = __float_as_int(v.x);
    int aa = g_sorted[s + (ij & 0xff)];
    int bb = g_sorted[s + (ij >> 8)];
    emit_one(out, off + k, (float)aa, (float)bb, v.y, v.z, v.w);
  }
}

// ---------------- launch ----------------
extern "C" void kernel_launch(void* const* d_in, const int* in_sizes, int n_in,
                              void* d_out, int out_size) {
  const float* coords = nullptr;
  for (int i = 0; i < n_in; i++)
    if (in_sizes[i] == 3*NA) coords = (const float*)d_in[i];
  float* out = (float*)d_out;

  k_zero    <<<(NC + 255)/256, 256>>>();
  k_assign  <<<(NA + 255)/256, 256>>>(coords);
  k_scan    <<<1, 1024>>>(0);                       // cnt -> start
  k_scatter <<<(NA + 255)/256, 256>>>();
  k_sortcell<<<(NC + 127)/128, 128>>>(coords);
  k_surround<<<(NA*32 + 255)/256, 256>>>(coords);   // single pass -> scrA, akept
  k_within  <<<(NC*32 + 255)/256, 256>>>();         // single pass -> scrW, wkept
  k_scan    <<<1, 1024>>>(1);                       // akept -> aoff, total -> g_totalS
  k_scan    <<<1, 1024>>>(2);                       // wkept -> woff (+base), -> g_totalAll
  k_tail    <<<(MP + 255)/256, 256>>>(out);         // zero padded tail only
  k_emitA   <<<(NA*32 + 255)/256, 256>>>(out);
  k_emitW   <<<(NC*32 + 255)/256, 256>>>(out);
}

// round 3
// speedup vs baseline: 5.3382x; 1.6115x over previous
#include <cuda_runtime.h>
#include <math.h>
#include <stdint.h>

#define NA 50000
#define GD 15
#define NC (GD*GD*GD)
#define MP 2000000
#define CAP_A 96
#define CAP_W 768
#define CAP_C 96
#define NB_SURR ((NA + 7) / 8)

// ---------------- scratch (no allocs allowed) ----------------
__device__ int    g_flat[NA];
__device__ int    g_cnt[NC];
__device__ int    g_start[NC];
__device__ int    g_fill[NC];
__device__ int    g_sorted[NA];            // atom ids in image (sorted) order
__device__ float4 g_sp4[NA];               // sorted coords + id bits in .w
__device__ int    g_akept[NA];
__device__ int    g_bsumA[NB_SURR];
__device__ int    g_boffA[NB_SURR];
__device__ int    g_wkept[NC];
__device__ int    g_woff[NC];
__device__ int    g_totalS;
__device__ int    g_totalAll;
__device__ float4 g_scrA[(size_t)NA * CAP_A];   // per-atom surround staging
__device__ float4 g_scrW[(size_t)NC * CAP_W];   // per-cell within staging

__constant__ int c_off[13][3] = {
  {-1,0,0},{-1,-1,0},{0,-1,0},{1,-1,0},{-1,1,-1},{0,1,-1},{1,1,-1},
  {-1,0,-1},{0,0,-1},{1,0,-1},{-1,-1,-1},{0,-1,-1},{1,-1,-1}};

// ---------------- setup kernels ----------------
__global__ void k_zero() {
  int i = blockIdx.x*blockDim.x + threadIdx.x;
  if (i < NC) { g_cnt[i] = 0; g_fill[i] = 0; }
}

__device__ __forceinline__ int cellcoord(double v) {
  const double inv = 1.0/80.0;
  double f = __dmul_rn(v, inv);
  f = f - floor(f);
  if (f >= 1.0) f -= 1.0;
  if (f <  0.0) f += 1.0;
  return (int)floor(__dmul_rn(f, (double)GD));
}

__global__ void k_assign(const float* __restrict__ coords) {
  int i = blockIdx.x*blockDim.x + threadIdx.x;
  if (i >= NA) return;
  int x = cellcoord((double)coords[3*i+0]);
  int y = cellcoord((double)coords[3*i+1]);
  int z = cellcoord((double)coords[3*i+2]);
  int f = (x*GD + y)*GD + z;
  g_flat[i] = f;
  atomicAdd(&g_cnt[f], 1);
}

// single-block exclusive scan.
// mode 0: cnt->start (n=NC)
// mode 2: wkept->woff base g_totalS (n=NC), grand total -> g_totalAll
// mode 3: bsumA->boffA (n=NB_SURR), total -> g_totalS
__global__ void k_scan(int mode) {
  const int* in; int* out; int n;
  if (mode == 0)      { in = g_cnt;   out = g_start; n = NC; }
  else if (mode == 3) { in = g_bsumA; out = g_boffA; n = NB_SURR; }
  else                { in = g_wkept; out = g_woff;  n = NC; }
  __shared__ int wsum[32];
  __shared__ int carry;
  int lane = threadIdx.x & 31, wid = threadIdx.x >> 5;
  int nw = blockDim.x >> 5;
  if (threadIdx.x == 0) carry = (mode == 2) ? g_totalS : 0;
  __syncthreads();
  for (int s0 = 0; s0 < n; s0 += blockDim.x) {
    int i = s0 + threadIdx.x;
    int v = (i < n) ? in[i] : 0;
    int x = v;
    #pragma unroll
    for (int o = 1; o < 32; o <<= 1) {
      int y = __shfl_up_sync(0xffffffffu, x, o);
      if (lane >= o) x += y;
    }
    if (lane == 31) wsum[wid] = x;
    __syncthreads();
    if (wid == 0) {
      int w = (lane < nw) ? wsum[lane] : 0;
      #pragma unroll
      for (int o = 1; o < 32; o <<= 1) {
        int y = __shfl_up_sync(0xffffffffu, w, o);
        if (lane >= o) w += y;
      }
      wsum[lane] = w;
    }
    __syncthreads();
    int bp  = wid ? wsum[wid-1] : 0;
    int tot = wsum[nw-1];
    if (i < n) out[i] = carry + bp + x - v;
    __syncthreads();
    if (threadIdx.x == 0) carry += tot;
    __syncthreads();
  }
  if (threadIdx.x == 0) {
    if (mode == 3) g_totalS   = carry;
    if (mode == 2) g_totalAll = carry;
  }
}

__global__ void k_scatter() {
  int i = blockIdx.x*blockDim.x + threadIdx.x;
  if (i >= NA) return;
  int f = g_flat[i];
  int slot = atomicAdd(&g_fill[f], 1);
  g_sorted[g_start[f] + slot] = i;
}

// warp-per-cell rank sort (stable order = ascending atom id; ids unique)
// builds g_sorted (sorted) + g_sp4 packed coords/id table
__global__ void __launch_bounds__(256) k_sortcell(const float* __restrict__ coords) {
  __shared__ int sid[8][CAP_C];
  int w = (blockIdx.x*blockDim.x + threadIdx.x) >> 5;
  int lane = threadIdx.x & 31;
  int wl = (threadIdx.x >> 5);
  if (w >= NC) return;
  int s = g_start[w], n = g_cnt[w];
  if (n > CAP_C) n = CAP_C;   // safety (statistically impossible to trigger)
  for (int k = lane; k < n; k += 32) sid[wl][k] = g_sorted[s+k];
  __syncwarp();
  for (int k = lane; k < n; k += 32) {
    int v = sid[wl][k];
    int rank = 0;
    for (int m = 0; m < n; m++) rank += (sid[wl][m] < v);
    g_sorted[s+rank] = v;
    g_sp4[s+rank] = make_float4(coords[3*v+0], coords[3*v+1], coords[3*v+2],
                                __int_as_float(v));
  }
}

// keep test: float fast path, exact float64 path near the boundary (matches numpy)
__device__ __forceinline__ bool keep_pair(float ax, float ay, float az,
                                          float bx, float by, float bz,
                                          float fsx, float fsy, float fsz,
                                          float& dx, float& dy, float& dz) {
  dx = (ax - bx) + fsx;
  dy = (ay - by) + fsy;
  dz = (az - bz) + fsz;
  float sq = dx*dx + dy*dy + dz*dz;
  if (sq <= 27.0290f) return true;     // (5.2 - 1e-3)^2
  if (sq >  27.0510f) return false;    // (5.2 + 1e-3)^2
  double ddx = __dadd_rn(__dsub_rn((double)ax, (double)bx), (double)fsx);
  double ddy = __dadd_rn(__dsub_rn((double)ay, (double)by), (double)fsy);
  double ddz = __dadd_rn(__dsub_rn((double)az, (double)bz), (double)fsz);
  double dsq = __dadd_rn(__dadd_rn(__dmul_rn(ddx,ddx), __dmul_rn(ddy,ddy)), __dmul_rn(ddz,ddz));
  return sqrt(dsq) <= 5.2;
}

// surround pairs, single pass: flattened 13-segment iteration, one warp per atom.
// order = atom asc -> offset 0..12 -> slot asc. Kept pairs staged in g_scrA.
__global__ void __launch_bounds__(256) k_surround(const float* __restrict__ coords) {
  const unsigned FULL = 0xffffffffu;
  int w = (blockIdx.x*blockDim.x + threadIdx.x) >> 5;
  int lane = threadIdx.x & 31;
  int wl = (threadIdx.x >> 5);
  __shared__ int sh_base[8][13];   // segS - cumBefore
  __shared__ int sh_end [8][13];   // inclusive prefix of counts
  __shared__ float sh_fsx[8][13], sh_fsy[8][13], sh_fsz[8][13];
  __shared__ int sh_wtot[8];
  int a = w;   // 6250 blocks * 8 warps = NA exactly; no guard needed
  float ax = coords[3*a+0], ay = coords[3*a+1], az = coords[3*a+2];
  int f = g_flat[a];
  int cz = f % GD, cy = (f / GD) % GD, cx = f / (GD*GD);

  int segC = 0, segS = 0;
  float fx = 0.f, fy = 0.f, fz = 0.f;
  if (lane < 13) {
    int nx = cx + c_off[lane][0], ny = cy + c_off[lane][1], nz = cz + c_off[lane][2];
    int sx = 0, sy = 0, sz = 0;
    if (nx < 0) { nx += GD; sx = 1; } else if (nx >= GD) { nx -= GD; sx = -1; }
    if (ny < 0) { ny += GD; sy = 1; } else if (ny >= GD) { ny -= GD; sy = -1; }
    if (nz < 0) { nz += GD; sz = 1; } else if (nz >= GD) { nz -= GD; sz = -1; }
    int nc = (nx*GD + ny)*GD + nz;
    segS = g_start[nc]; segC = g_cnt[nc];
    fx = (float)sx * 80.0f; fy = (float)sy * 80.0f; fz = (float)sz * 80.0f;
  }
  // inclusive prefix of segC over lanes
  int pre = segC;
  #pragma unroll
  for (int o = 1; o < 16; o <<= 1) {
    int y = __shfl_up_sync(FULL, pre, o);
    if (lane >= o) pre += y;
  }
  int total = __shfl_sync(FULL, pre, 12);
  if (lane < 13) {
    sh_base[wl][lane] = segS - (pre - segC);
    sh_end [wl][lane] = pre;
    sh_fsx [wl][lane] = fx;
    sh_fsy [wl][lane] = fy;
    sh_fsz [wl][lane] = fz;
  }
  __syncwarp();

  float4* scr = &g_scrA[(size_t)a * CAP_A];
  int wp = 0;
  int o = 0;                      // monotone per-lane segment cursor
  for (int t0 = 0; t0 < total; t0 += 32) {
    int t = t0 + lane;
    bool kp = false; float bid = 0.f; float dx = 0.f, dy = 0.f, dz = 0.f;
    if (t < total) {
      while (o < 12 && t >= sh_end[wl][o]) o++;
      int j = sh_base[wl][o] + t;
      float4 v = g_sp4[j];
      kp = keep_pair(ax, ay, az, v.x, v.y, v.z,
                     sh_fsx[wl][o], sh_fsy[wl][o], sh_fsz[wl][o], dx, dy, dz);
      bid = v.w;
    }
    unsigned m = __ballot_sync(FULL, kp);
    if (kp) {
      int p = wp + __popc(m & ((1u << lane) - 1u));
      scr[p] = make_float4(bid, dx, dy, dz);
    }
    wp += __popc(m);
  }
  if (lane == 0) { g_akept[a] = wp; sh_wtot[wl] = wp; }
  __syncthreads();
  if (threadIdx.x == 0) {
    int tsum = 0;
    #pragma unroll
    for (int q = 0; q < 8; q++) tsum += sh_wtot[q];
    g_bsumA[blockIdx.x] = tsum;
  }
}

// within-cell pairs, single pass: one warp per cell; tril order; staged in g_scrW
__global__ void __launch_bounds__(256) k_within() {
  const unsigned FULL = 0xffffffffu;
  int w = (blockIdx.x*blockDim.x + threadIdx.x) >> 5;
  int lane = threadIdx.x & 31;
  if (w >= NC) return;
  int s = g_start[w], c = g_cnt[w];
  int T = c*(c-1)/2;
  float4* scr = &g_scrW[(size_t)w * CAP_W];
  int wp = 0;
  for (int t0 = 0; t0 < T; t0 += 32) {
    int t = t0 + lane;
    bool kp = false; int ij = 0; float dx = 0.f, dy = 0.f, dz = 0.f;
    if (t < T) {
      int i = (int)((1.0f + sqrtf(8.0f*(float)t + 1.0f)) * 0.5f);
      while (i*(i-1)/2 > t) i--;
      while ((i+1)*i/2 <= t) i++;
      int j = t - i*(i-1)/2;
      float4 va = g_sp4[s+i];
      float4 vb = g_sp4[s+j];
      kp = keep_pair(va.x, va.y, va.z, vb.x, vb.y, vb.z, 0.f, 0.f, 0.f, dx, dy, dz);
      ij = i | (j << 8);
    }
    unsigned m = __ballot_sync(FULL, kp);
    if (kp) {
      int p = wp + __popc(m & ((1u << lane) - 1u));
      scr[p] = make_float4(__int_as_float(ij), dx, dy, dz);
    }
    wp += __popc(m);
  }
  if (lane == 0) g_wkept[w] = wp;
}

// zero only the padded tail [totalAll, MP); fixed grid, grid-stride
__global__ void k_tail(float* __restrict__ out) {
  __shared__ int sh_total;
  if (threadIdx.x == 0) sh_total = g_totalAll;
  __syncthreads();
  int stride = gridDim.x * blockDim.x;
  for (int i = sh_total + blockIdx.x*blockDim.x + threadIdx.x; i < MP; i += stride) {
    out[i]        = 0.f;
    out[MP + i]   = 0.f;
    out[2*MP + i] = 0.f;
    out[3*MP + 3*i + 0] = 0.f;
    out[3*MP + 3*i + 1] = 0.f;
    out[3*MP + 3*i + 2] = 0.f;
    out[6*MP + i] = 0.f;
  }
}

__device__ __forceinline__ void emit_one(float* __restrict__ out, int p,
                                         float fa, float fb,
                                         float dx, float dy, float dz) {
  out[p]        = fa;
  out[MP + p]   = fb;
  out[2*MP + p] = sqrtf(dx*dx + dy*dy + dz*dz);
  out[3*MP + 3*p + 0] = dx;
  out[3*MP + 3*p + 1] = dy;
  out[3*MP + 3*p + 2] = dz;
  out[6*MP + p] = 1.0f;
}

__global__ void __launch_bounds__(256) k_emitA(float* __restrict__ out) {
  const unsigned FULL = 0xffffffffu;
  int w = (blockIdx.x*blockDim.x + threadIdx.x) >> 5;
  int lane = threadIdx.x & 31;
  if (w >= NA) return;
  int a = w;
  int a0 = a & ~7;
  int cnt = (lane < 8) ? g_akept[a0 + lane] : 0;
  int pre = cnt;
  #pragma unroll
  for (int o = 1; o < 8; o <<= 1) {
    int y = __shfl_up_sync(FULL, pre, o);
    if (lane >= o) pre += y;
  }
  int m = a & 7;
  int excl = __shfl_sync(FULL, pre - cnt, m);
  int n    = __shfl_sync(FULL, cnt, m);
  int off  = g_boffA[a >> 3] + excl;
  const float4* scr = &g_scrA[(size_t)a * CAP_A];
  float fa = (float)a;
  for (int k = lane; k < n; k += 32) {
    float4 v = scr[k];
    emit_one(out, off + k, fa, (float)__float_as_int(v.x), v.y, v.z, v.w);
  }
}

__global__ void __launch_bounds__(256) k_emitW(float* __restrict__ out) {
  int w = (blockIdx.x*blockDim.x + threadIdx.x) >> 5;
  int lane = threadIdx.x & 31;
  if (w >= NC) return;
  int n = g_wkept[w], off = g_woff[w], s = g_start[w];
  const float4* scr = &g_scrW[(size_t)w * CAP_W];
  for (int k = lane; k < n; k += 32) {
    float4 v = scr[k];
    int ij = __float_as_int(v.x);
    int aa = g_sorted[s + (ij & 0xff)];
    int bb = g_sorted[s + (ij >> 8)];
    emit_one(out, off + k, (float)aa, (float)bb, v.y, v.z, v.w);
  }
}

// ---------------- launch ----------------
extern "C" void kernel_launch(void* const* d_in, const int* in_sizes, int n_in,
                              void* d_out, int out_size) {
  const float* coords = nullptr;
  for (int i = 0; i < n_in; i++)
    if (in_sizes[i] == 3*NA) coords = (const float*)d_in[i];
  float* out = (float*)d_out;

  k_zero    <<<(NC + 255)/256, 256>>>();
  k_assign  <<<(NA + 255)/256, 256>>>(coords);
  k_scan    <<<1, 1024>>>(0);                        // cnt -> start
  k_scatter <<<(NA + 255)/256, 256>>>();
  k_sortcell<<<(NC*32 + 255)/256, 256>>>(coords);    // warp/cell rank sort + g_sp4
  k_surround<<<NB_SURR, 256>>>(coords);              // -> scrA, akept, bsumA
  k_scan    <<<1, 1024>>>(3);                        // bsumA -> boffA, totalS
  k_within  <<<(NC*32 + 255)/256, 256>>>();          // -> scrW, wkept
  k_scan    <<<1, 1024>>>(2);                        // wkept -> woff (+totalS), totalAll
  k_tail    <<<1024, 256>>>(out);                    // zero padded tail only
  k_emitA   <<<(NA*32 + 255)/256, 256>>>(out);
  k_emitW   <<<(NC*32 + 255)/256, 256>>>(out);
}

// round 4
// speedup vs baseline: 6.4492x; 1.2081x over previous
#include <cuda_runtime.h>
#include <math.h>
#include <stdint.h>

#define NA 50000
#define GD 15
#define NC (GD*GD*GD)
#define MP 2000000
#define CAP_A 96
#define CAP_W 768
#define CAP_C 64
#define NB_SURR ((NA + 7) / 8)          // 6250 blocks, 8 atoms each
#define NB_WITH ((NC + 7) / 8)          // 422 blocks, 8 cells each
#define NB_TAIL 256

// ---------------- scratch (no allocs allowed; zero-init at load) ----------------
__device__ int    g_flat[NA];
__device__ int    g_cnt[NC];                       // MUST be zero at launch start (re-zeroed at end)
__device__ float4 g_cell4[(size_t)NC * CAP_C];     // unsorted per-cell (x,y,z,idbits)
__device__ float4 g_sp4[(size_t)NC * CAP_C];       // id-sorted per-cell
__device__ int    g_akept[NA];
__device__ int    g_bsumA[NB_SURR];
__device__ int    g_boffA[NB_SURR];
__device__ int    g_wkept[NC];
__device__ int    g_woff[NC];
__device__ int    g_totalAll;
__device__ float4 g_scrA[(size_t)NA * CAP_A];      // per-atom surround staging
__device__ float4 g_scrW[(size_t)NC * CAP_W];      // per-cell within staging

__constant__ int c_off[13][3] = {
  {-1,0,0},{-1,-1,0},{0,-1,0},{1,-1,0},{-1,1,-1},{0,1,-1},{1,1,-1},
  {-1,0,-1},{0,0,-1},{1,0,-1},{-1,-1,-1},{0,-1,-1},{1,-1,-1}};

// ---------------- helpers ----------------
__device__ __forceinline__ int cellcoord(double v) {
  const double inv = 1.0/80.0;
  double f = __dmul_rn(v, inv);
  f = f - floor(f);
  if (f >= 1.0) f -= 1.0;
  if (f <  0.0) f += 1.0;
  return (int)floor(__dmul_rn(f, (double)GD));
}

// keep test: float fast path, exact float64 path near the boundary (matches numpy)
__device__ __forceinline__ bool keep_pair(float ax, float ay, float az,
                                          float bx, float by, float bz,
                                          float fsx, float fsy, float fsz,
                                          float& dx, float& dy, float& dz) {
  dx = (ax - bx) + fsx;
  dy = (ay - by) + fsy;
  dz = (az - bz) + fsz;
  float sq = dx*dx + dy*dy + dz*dz;
  if (sq <= 27.0290f) return true;     // (5.2 - 1e-3)^2
  if (sq >  27.0510f) return false;    // (5.2 + 1e-3)^2
  double ddx = __dadd_rn(__dsub_rn((double)ax, (double)bx), (double)fsx);
  double ddy = __dadd_rn(__dsub_rn((double)ay, (double)by), (double)fsy);
  double ddz = __dadd_rn(__dsub_rn((double)az, (double)bz), (double)fsz);
  double dsq = __dadd_rn(__dadd_rn(__dmul_rn(ddx,ddx), __dmul_rn(ddy,ddy)), __dmul_rn(ddz,ddz));
  return sqrt(dsq) <= 5.2;
}

// ---------------- 1. assign: cell id + fixed-stride staging ----------------
__global__ void k_assign(const float* __restrict__ coords) {
  int i = blockIdx.x*blockDim.x + threadIdx.x;
  if (i >= NA) return;
  float x = coords[3*i+0], y = coords[3*i+1], z = coords[3*i+2];
  int cx = cellcoord((double)x);
  int cy = cellcoord((double)y);
  int cz = cellcoord((double)z);
  int f = (cx*GD + cy)*GD + cz;
  g_flat[i] = f;
  int slot = atomicAdd(&g_cnt[f], 1);
  if (slot < CAP_C)
    g_cell4[f*CAP_C + slot] = make_float4(x, y, z, __int_as_float(i));
}

// ---------------- 2. per-cell id rank-sort (stable order = ascending id) ------
__global__ void __launch_bounds__(256) k_sortcell() {
  __shared__ float4 sc[8][CAP_C];
  int w = (blockIdx.x*blockDim.x + threadIdx.x) >> 5;
  int lane = threadIdx.x & 31;
  int wl = threadIdx.x >> 5;
  if (w >= NC) return;
  int n = g_cnt[w]; if (n > CAP_C) n = CAP_C;
  int s = w * CAP_C;
  for (int k = lane; k < n; k += 32) sc[wl][k] = g_cell4[s+k];
  __syncwarp();
  for (int k = lane; k < n; k += 32) {
    float4 v = sc[wl][k];
    int id = __float_as_int(v.w);
    int rank = 0;
    for (int m = 0; m < n; m++) rank += (__float_as_int(sc[wl][m].w) < id);
    g_sp4[s+rank] = v;
  }
}

// ---------------- 3. pairs: surround (blocks < NB_SURR) + within --------------
__global__ void __launch_bounds__(256) k_pairs(const float* __restrict__ coords) {
  const unsigned FULL = 0xffffffffu;
  int lane = threadIdx.x & 31;
  int wl = threadIdx.x >> 5;
  __shared__ int   sh_base[8][13];
  __shared__ int   sh_end [8][13];
  __shared__ float sh_fsx[8][13], sh_fsy[8][13], sh_fsz[8][13];
  __shared__ int   sh_wtot[8];

  if (blockIdx.x < NB_SURR) {
    // ---- surround: one warp per atom; order = atom asc -> offset 0..12 -> slot asc
    int a = blockIdx.x*8 + wl;            // 6250*8 = NA exactly
    float ax = coords[3*a+0], ay = coords[3*a+1], az = coords[3*a+2];
    int f = g_flat[a];
    int cz = f % GD, cy = (f / GD) % GD, cx = f / (GD*GD);

    int segC = 0, segB = 0;
    float fx = 0.f, fy = 0.f, fz = 0.f;
    if (lane < 13) {
      int nx = cx + c_off[lane][0], ny = cy + c_off[lane][1], nz = cz + c_off[lane][2];
      int sx = 0, sy = 0, sz = 0;
      if (nx < 0) { nx += GD; sx = 1; } else if (nx >= GD) { nx -= GD; sx = -1; }
      if (ny < 0) { ny += GD; sy = 1; } else if (ny >= GD) { ny -= GD; sy = -1; }
      if (nz < 0) { nz += GD; sz = 1; } else if (nz >= GD) { nz -= GD; sz = -1; }
      int nc = (nx*GD + ny)*GD + nz;
      segB = nc * CAP_C;
      segC = g_cnt[nc]; if (segC > CAP_C) segC = CAP_C;
      fx = (float)sx * 80.0f; fy = (float)sy * 80.0f; fz = (float)sz * 80.0f;
    }
    int pre = segC;
    #pragma unroll
    for (int o = 1; o < 16; o <<= 1) {
      int y = __shfl_up_sync(FULL, pre, o);
      if (lane >= o) pre += y;
    }
    int total = __shfl_sync(FULL, pre, 12);
    if (lane < 13) {
      sh_base[wl][lane] = segB - (pre - segC);
      sh_end [wl][lane] = pre;
      sh_fsx [wl][lane] = fx;
      sh_fsy [wl][lane] = fy;
      sh_fsz [wl][lane] = fz;
    }
    __syncwarp();

    float4* scr = &g_scrA[(size_t)a * CAP_A];
    int wp = 0;
    int o = 0;                            // monotone per-lane segment cursor
    for (int t0 = 0; t0 < total; t0 += 32) {
      int t = t0 + lane;
      bool kp = false; float bid = 0.f; float dx = 0.f, dy = 0.f, dz = 0.f;
      if (t < total) {
        while (o < 12 && t >= sh_end[wl][o]) o++;
        int j = sh_base[wl][o] + t;
        float4 v = g_sp4[j];
        kp = keep_pair(ax, ay, az, v.x, v.y, v.z,
                       sh_fsx[wl][o], sh_fsy[wl][o], sh_fsz[wl][o], dx, dy, dz);
        bid = v.w;
      }
      unsigned m = __ballot_sync(FULL, kp);
      if (kp) {
        int p = wp + __popc(m & ((1u << lane) - 1u));
        scr[p] = make_float4(bid, dx, dy, dz);
      }
      wp += __popc(m);
    }
    if (lane == 0) { g_akept[a] = wp; sh_wtot[wl] = wp; }
    __syncthreads();
    if (threadIdx.x == 0) {
      int tsum = 0;
      #pragma unroll
      for (int q = 0; q < 8; q++) tsum += sh_wtot[q];
      g_bsumA[blockIdx.x] = tsum;
    }
  } else {
    // ---- within: one warp per cell; tril order (i asc, j asc, i>j)
    int w = (blockIdx.x - NB_SURR)*8 + wl;
    if (w >= NC) return;
    int s = w * CAP_C;
    int c = g_cnt[w]; if (c > CAP_C) c = CAP_C;
    int T = c*(c-1)/2;
    float4* scr = &g_scrW[(size_t)w * CAP_W];
    int wp = 0;
    for (int t0 = 0; t0 < T; t0 += 32) {
      int t = t0 + lane;
      bool kp = false; int ij = 0; float dx = 0.f, dy = 0.f, dz = 0.f;
      if (t < T) {
        int i = (int)((1.0f + sqrtf(8.0f*(float)t + 1.0f)) * 0.5f);
        while (i*(i-1)/2 > t) i--;
        while ((i+1)*i/2 <= t) i++;
        int j = t - i*(i-1)/2;
        float4 va = g_sp4[s+i];
        float4 vb = g_sp4[s+j];
        kp = keep_pair(va.x, va.y, va.z, vb.x, vb.y, vb.z, 0.f, 0.f, 0.f, dx, dy, dz);
        ij = i | (j << 8);
      }
      unsigned m = __ballot_sync(FULL, kp);
      if (kp) {
        int p = wp + __popc(m & ((1u << lane) - 1u));
        scr[p] = make_float4(__int_as_float(ij), dx, dy, dz);
      }
      wp += __popc(m);
    }
    if (lane == 0) g_wkept[w] = wp;
  }
}

// ---------------- 4. both scans, one single-block kernel ----------------------
__device__ __forceinline__ void scan_phase(const int* __restrict__ in, int* __restrict__ out,
                                           int n, int* wsum, int* carry) {
  int lane = threadIdx.x & 31, wid = threadIdx.x >> 5;
  int nw = blockDim.x >> 5;
  for (int s0 = 0; s0 < n; s0 += blockDim.x) {
    int i = s0 + threadIdx.x;
    int v = (i < n) ? in[i] : 0;
    int x = v;
    #pragma unroll
    for (int o = 1; o < 32; o <<= 1) {
      int y = __shfl_up_sync(0xffffffffu, x, o);
      if (lane >= o) x += y;
    }
    if (lane == 31) wsum[wid] = x;
    __syncthreads();
    if (wid == 0) {
      int w = (lane < nw) ? wsum[lane] : 0;
      #pragma unroll
      for (int o = 1; o < 32; o <<= 1) {
        int y = __shfl_up_sync(0xffffffffu, w, o);
        if (lane >= o) w += y;
      }
      wsum[lane] = w;
    }
    __syncthreads();
    int bp  = wid ? wsum[wid-1] : 0;
    int tot = wsum[nw-1];
    if (i < n) out[i] = *carry + bp + x - v;
    __syncthreads();
    if (threadIdx.x == 0) *carry += tot;
    __syncthreads();
  }
}

__global__ void k_scan2() {
  __shared__ int wsum[32];
  __shared__ int carry;
  if (threadIdx.x == 0) carry = 0;
  __syncthreads();
  scan_phase(g_bsumA, g_boffA, NB_SURR, wsum, &carry);  // surround totals first
  scan_phase(g_wkept, g_woff,  NC,      wsum, &carry);  // within, base = totalS
  if (threadIdx.x == 0) g_totalAll = carry;
}

// ---------------- 5. emit: emitA + emitW + tail/zero, one grid ----------------
__device__ __forceinline__ void emit_one(float* __restrict__ out, int p,
                                         float fa, float fb,
                                         float dx, float dy, float dz) {
  out[p]        = fa;
  out[MP + p]   = fb;
  out[2*MP + p] = sqrtf(dx*dx + dy*dy + dz*dz);
  out[3*MP + 3*p + 0] = dx;
  out[3*MP + 3*p + 1] = dy;
  out[3*MP + 3*p + 2] = dz;
  out[6*MP + p] = 1.0f;
}

__global__ void __launch_bounds__(256) k_emit(float* __restrict__ out) {
  const unsigned FULL = 0xffffffffu;
  int lane = threadIdx.x & 31;
  int wl = threadIdx.x >> 5;

  if (blockIdx.x < NB_SURR) {
    // emit surround pairs for 8 atoms
    int a = blockIdx.x*8 + wl;
    int cnt = (lane < 8) ? g_akept[blockIdx.x*8 + lane] : 0;
    int pre = cnt;
    #pragma unroll
    for (int o = 1; o < 8; o <<= 1) {
      int y = __shfl_up_sync(FULL, pre, o);
      if (lane >= o) pre += y;
    }
    int excl = __shfl_sync(FULL, pre - cnt, wl);
    int n    = __shfl_sync(FULL, cnt, wl);
    int off  = g_boffA[blockIdx.x] + excl;
    const float4* scr = &g_scrA[(size_t)a * CAP_A];
    float fa = (float)a;
    for (int k = lane; k < n; k += 32) {
      float4 v = scr[k];
      emit_one(out, off + k, fa, (float)__float_as_int(v.x), v.y, v.z, v.w);
    }
  } else if (blockIdx.x < NB_SURR + NB_WITH) {
    // emit within pairs for 8 cells
    int w = (blockIdx.x - NB_SURR)*8 + wl;
    if (w >= NC) return;
    int n = g_wkept[w], off = g_woff[w], s = w * CAP_C;
    const float4* scr = &g_scrW[(size_t)w * CAP_W];
    for (int k = lane; k < n; k += 32) {
      float4 v = scr[k];
      int ij = __float_as_int(v.x);
      float fa = (float)__float_as_int(g_sp4[s + (ij & 0xff)].w);
      float fb = (float)__float_as_int(g_sp4[s + (ij >> 8)].w);
      emit_one(out, off + k, fa, fb, v.y, v.z, v.w);
    }
  } else {
    // tail zeroing of [totalAll, MP) + re-zero g_cnt for the next replay
    int tb = blockIdx.x - NB_SURR - NB_WITH;     // 0..NB_TAIL-1
    int zi = tb*blockDim.x + threadIdx.x;
    if (zi < NC) g_cnt[zi] = 0;
    __shared__ int sh_total;
    if (threadIdx.x == 0) sh_total = g_totalAll;
    __syncthreads();
    int stride = NB_TAIL * blockDim.x;
    for (int i = sh_total + tb*blockDim.x + threadIdx.x; i < MP; i += stride) {
      out[i]        = 0.f;
      out[MP + i]   = 0.f;
      out[2*MP + i] = 0.f;
      out[3*MP + 3*i + 0] = 0.f;
      out[3*MP + 3*i + 1] = 0.f;
      out[3*MP + 3*i + 2] = 0.f;
      out[6*MP + i] = 0.f;
    }
  }
}

// ---------------- launch ----------------
extern "C" void kernel_launch(void* const* d_in, const int* in_sizes, int n_in,
                              void* d_out, int out_size) {
  const float* coords = nullptr;
  for (int i = 0; i < n_in; i++)
    if (in_sizes[i] == 3*NA) coords = (const float*)d_in[i];
  float* out = (float*)d_out;

  k_assign  <<<(NA + 255)/256, 256>>>(coords);           // cells + fixed-stride staging
  k_sortcell<<<NB_WITH, 256>>>();                        // per-cell id sort -> g_sp4
  k_pairs   <<<NB_SURR + NB_WITH, 256>>>(coords);        // surround + within, staged
  k_scan2   <<<1, 1024>>>();                             // both offset scans
  k_emit    <<<NB_SURR + NB_WITH + NB_TAIL, 256>>>(out); // emit + tail + counter reset
}

// round 5
// speedup vs baseline: 7.0643x; 1.0954x over previous
#include <cuda_runtime.h>
#include <math.h>
#include <stdint.h>

#define NA 50000
#define GD 15
#define NC (GD*GD*GD)
#define MP 2000000
#define CAP_A 96
#define CAP_W 768
#define CAP_C 64
#define NB_SURR ((NA + 7) / 8)          // 6250 blocks, 8 atoms each
#define NB_WITH ((NC + 7) / 8)          // 422 blocks, 8 cells each
#define NB      (NB_SURR + NB_WITH)     // 6672 pair blocks
#define NCB     ((NB + 31) / 32)        // 209 coarse bins
#define NB_TAIL 256

// ---------------- scratch (no allocs; zero-init at load) ----------------
__device__ int    g_flat[NA];
__device__ int    g_cnt[NC];                       // zero at replay start (re-zeroed in emit tail)
__device__ float4 g_cell4[(size_t)NC * CAP_C];     // unsorted per-cell (x,y,z,idbits)
__device__ float4 g_sp4[(size_t)NC * CAP_C];       // id-sorted per-cell
__device__ int    g_akept[NA];
__device__ int    g_wkept[NC];
__device__ int    g_btot[NB];                      // per-pair-block kept totals
__device__ int    g_csum[NCB];                     // coarse bin sums (zeroed in k_assign)
__device__ float4 g_scrA[(size_t)NA * CAP_A];      // per-atom surround staging
__device__ float4 g_scrW[(size_t)NC * CAP_W];      // per-cell within staging

__constant__ int c_off[13][3] = {
  {-1,0,0},{-1,-1,0},{0,-1,0},{1,-1,0},{-1,1,-1},{0,1,-1},{1,1,-1},
  {-1,0,-1},{0,0,-1},{1,0,-1},{-1,-1,-1},{0,-1,-1},{1,-1,-1}};

// ---------------- helpers ----------------
__device__ __forceinline__ int cellcoord(double v) {
  const double inv = 1.0/80.0;
  double f = __dmul_rn(v, inv);
  f = f - floor(f);
  if (f >= 1.0) f -= 1.0;
  if (f <  0.0) f += 1.0;
  return (int)floor(__dmul_rn(f, (double)GD));
}

__device__ __forceinline__ bool keep_pair(float ax, float ay, float az,
                                          float bx, float by, float bz,
                                          float fsx, float fsy, float fsz,
                                          float& dx, float& dy, float& dz) {
  dx = (ax - bx) + fsx;
  dy = (ay - by) + fsy;
  dz = (az - bz) + fsz;
  float sq = dx*dx + dy*dy + dz*dz;
  if (sq <= 27.0290f) return true;     // (5.2 - 1e-3)^2
  if (sq >  27.0510f) return false;    // (5.2 + 1e-3)^2
  double ddx = __dadd_rn(__dsub_rn((double)ax, (double)bx), (double)fsx);
  double ddy = __dadd_rn(__dsub_rn((double)ay, (double)by), (double)fsy);
  double ddz = __dadd_rn(__dsub_rn((double)az, (double)bz), (double)fsz);
  double dsq = __dadd_rn(__dadd_rn(__dmul_rn(ddx,ddx), __dmul_rn(ddy,ddy)), __dmul_rn(ddz,ddz));
  return sqrt(dsq) <= 5.2;
}

// ---------------- 1. assign: cell id + fixed-stride staging -------------------
__global__ void k_assign(const float* __restrict__ coords) {
  int i = blockIdx.x*blockDim.x + threadIdx.x;
  if (blockIdx.x == 0 && threadIdx.x < NCB) g_csum[threadIdx.x] = 0;  // reset for this replay
  if (i >= NA) return;
  float x = coords[3*i+0], y = coords[3*i+1], z = coords[3*i+2];
  int cx = cellcoord((double)x);
  int cy = cellcoord((double)y);
  int cz = cellcoord((double)z);
  int f = (cx*GD + cy)*GD + cz;
  g_flat[i] = f;
  int slot = atomicAdd(&g_cnt[f], 1);
  if (slot < CAP_C)
    g_cell4[f*CAP_C + slot] = make_float4(x, y, z, __int_as_float(i));
}

// ---------------- 2. per-cell id rank-sort (stable = ascending id) ------------
__global__ void __launch_bounds__(256) k_sortcell() {
  __shared__ float4 sc[8][CAP_C];
  int w = (blockIdx.x*blockDim.x + threadIdx.x) >> 5;
  int lane = threadIdx.x & 31;
  int wl = threadIdx.x >> 5;
  if (w >= NC) return;
  int n = g_cnt[w]; if (n > CAP_C) n = CAP_C;
  int s = w * CAP_C;
  for (int k = lane; k < n; k += 32) sc[wl][k] = g_cell4[s+k];
  __syncwarp();
  for (int k = lane; k < n; k += 32) {
    float4 v = sc[wl][k];
    int id = __float_as_int(v.w);
    int rank = 0;
    for (int m = 0; m < n; m++) rank += (__float_as_int(sc[wl][m].w) < id);
    g_sp4[s+rank] = v;
  }
}

// ---------------- 3. pairs: surround (blocks < NB_SURR) + within --------------
__global__ void __launch_bounds__(256) k_pairs(const float* __restrict__ coords) {
  const unsigned FULL = 0xffffffffu;
  int lane = threadIdx.x & 31;
  int wl = threadIdx.x >> 5;
  __shared__ int   sh_base[8][13];
  __shared__ int   sh_end [8][13];
  __shared__ float sh_fsx[8][13], sh_fsy[8][13], sh_fsz[8][13];
  __shared__ int   sh_wtot[8];

  if (blockIdx.x < NB_SURR) {
    // surround: warp per atom; order = atom asc -> offset 0..12 -> slot asc
    int a = blockIdx.x*8 + wl;            // 6250*8 = NA exactly
    float ax = coords[3*a+0], ay = coords[3*a+1], az = coords[3*a+2];
    int f = g_flat[a];
    int cz = f % GD, cy = (f / GD) % GD, cx = f / (GD*GD);

    int segC = 0, segB = 0;
    float fx = 0.f, fy = 0.f, fz = 0.f;
    if (lane < 13) {
      int nx = cx + c_off[lane][0], ny = cy + c_off[lane][1], nz = cz + c_off[lane][2];
      int sx = 0, sy = 0, sz = 0;
      if (nx < 0) { nx += GD; sx = 1; } else if (nx >= GD) { nx -= GD; sx = -1; }
      if (ny < 0) { ny += GD; sy = 1; } else if (ny >= GD) { ny -= GD; sy = -1; }
      if (nz < 0) { nz += GD; sz = 1; } else if (nz >= GD) { nz -= GD; sz = -1; }
      int nc = (nx*GD + ny)*GD + nz;
      segB = nc * CAP_C;
      segC = g_cnt[nc]; if (segC > CAP_C) segC = CAP_C;
      fx = (float)sx * 80.0f; fy = (float)sy * 80.0f; fz = (float)sz * 80.0f;
    }
    int pre = segC;
    #pragma unroll
    for (int o = 1; o < 16; o <<= 1) {
      int y = __shfl_up_sync(FULL, pre, o);
      if (lane >= o) pre += y;
    }
    int total = __shfl_sync(FULL, pre, 12);
    if (lane < 13) {
      sh_base[wl][lane] = segB - (pre - segC);
      sh_end [wl][lane] = pre;
      sh_fsx [wl][lane] = fx;
      sh_fsy [wl][lane] = fy;
      sh_fsz [wl][lane] = fz;
    }
    __syncwarp();

    float4* scr = &g_scrA[(size_t)a * CAP_A];
    int wp = 0;
    int o = 0;                            // monotone per-lane segment cursor
    for (int t0 = 0; t0 < total; t0 += 32) {
      int t = t0 + lane;
      bool kp = false; float bid = 0.f; float dx = 0.f, dy = 0.f, dz = 0.f;
      if (t < total) {
        while (o < 12 && t >= sh_end[wl][o]) o++;
        int j = sh_base[wl][o] + t;
        float4 v = g_sp4[j];
        kp = keep_pair(ax, ay, az, v.x, v.y, v.z,
                       sh_fsx[wl][o], sh_fsy[wl][o], sh_fsz[wl][o], dx, dy, dz);
        bid = v.w;
      }
      unsigned m = __ballot_sync(FULL, kp);
      if (kp) {
        int p = wp + __popc(m & ((1u << lane) - 1u));
        scr[p] = make_float4(bid, dx, dy, dz);
      }
      wp += __popc(m);
    }
    if (lane == 0) { g_akept[a] = wp; sh_wtot[wl] = wp; }
    __syncthreads();
    if (threadIdx.x == 0) {
      int tsum = 0;
      #pragma unroll
      for (int q = 0; q < 8; q++) tsum += sh_wtot[q];
      g_btot[blockIdx.x] = tsum;
      atomicAdd(&g_csum[blockIdx.x >> 5], tsum);
    }
  } else {
    // within: warp per cell; tril order (i asc, j asc, i>j)
    int w = (blockIdx.x - NB_SURR)*8 + wl;
    int wp = 0;
    if (w < NC) {
      int s = w * CAP_C;
      int c = g_cnt[w]; if (c > CAP_C) c = CAP_C;
      int T = c*(c-1)/2;
      float4* scr = &g_scrW[(size_t)w * CAP_W];
      for (int t0 = 0; t0 < T; t0 += 32) {
        int t = t0 + lane;
        bool kp = false; int ij = 0; float dx = 0.f, dy = 0.f, dz = 0.f;
        if (t < T) {
          int i = (int)((1.0f + sqrtf(8.0f*(float)t + 1.0f)) * 0.5f);
          while (i*(i-1)/2 > t) i--;
          while ((i+1)*i/2 <= t) i++;
          int j = t - i*(i-1)/2;
          float4 va = g_sp4[s+i];
          float4 vb = g_sp4[s+j];
          kp = keep_pair(va.x, va.y, va.z, vb.x, vb.y, vb.z, 0.f, 0.f, 0.f, dx, dy, dz);
          ij = i | (j << 8);
        }
        unsigned m = __ballot_sync(FULL, kp);
        if (kp) {
          int p = wp + __popc(m & ((1u << lane) - 1u));
          scr[p] = make_float4(__int_as_float(ij), dx, dy, dz);
        }
        wp += __popc(m);
      }
      if (lane == 0) g_wkept[w] = wp;
    }
    if (lane == 0) sh_wtot[wl] = wp;
    __syncthreads();
    if (threadIdx.x == 0) {
      int tsum = 0;
      #pragma unroll
      for (int q = 0; q < 8; q++) tsum += sh_wtot[q];
      g_btot[blockIdx.x] = tsum;
      atomicAdd(&g_csum[blockIdx.x >> 5], tsum);
    }
  }
}

// ---------------- 4. emit: per-block decentralized base + emit + tail ---------
__device__ __forceinline__ void emit_one(float* __restrict__ out, int p,
                                         float fa, float fb,
                                         float dx, float dy, float dz) {
  out[p]        = fa;
  out[MP + p]   = fb;
  out[2*MP + p] = sqrtf(dx*dx + dy*dy + dz*dz);
  out[3*MP + 3*p + 0] = dx;
  out[3*MP + 3*p + 1] = dy;
  out[3*MP + 3*p + 2] = dz;
  out[6*MP + p] = 1.0f;
}

__device__ __forceinline__ int warp_sum32(int v) {
  #pragma unroll
  for (int o = 16; o >= 1; o >>= 1) v += __shfl_down_sync(0xffffffffu, v, o);
  return v;
}

__global__ void __launch_bounds__(256) k_emit(float* __restrict__ out) {
  const unsigned FULL = 0xffffffffu;
  int lane = threadIdx.x & 31;
  int wl = threadIdx.x >> 5;
  __shared__ int sh_blockbase;

  int b = blockIdx.x;
  if (b < NB) {
    // warp 0: block base = coarse prefix + fine prefix within bin
    if (wl == 0) {
      int cb = b >> 5;
      int coarse = 0;
      for (int q = lane; q < NCB; q += 32) coarse += (q < cb) ? g_csum[q] : 0;
      int fine = (lane < (b & 31)) ? g_btot[(cb << 5) + lane] : 0;
      int base = warp_sum32(coarse + fine);
      if (lane == 0) sh_blockbase = base;
    }
    __syncthreads();
    int blockbase = sh_blockbase;

    if (b < NB_SURR) {
      // emit surround pairs for 8 atoms
      int a = b*8 + wl;
      int cnt = (lane < 8) ? g_akept[b*8 + lane] : 0;
      int pre = cnt;
      #pragma unroll
      for (int o = 1; o < 8; o <<= 1) {
        int y = __shfl_up_sync(FULL, pre, o);
        if (lane >= o) pre += y;
      }
      int excl = __shfl_sync(FULL, pre - cnt, wl);
      int n    = __shfl_sync(FULL, cnt, wl);
      int off  = blockbase + excl;
      const float4* scr = &g_scrA[(size_t)a * CAP_A];
      float fa = (float)a;
      for (int k = lane; k < n; k += 32) {
        float4 v = scr[k];
        emit_one(out, off + k, fa, (float)__float_as_int(v.x), v.y, v.z, v.w);
      }
    } else {
      // emit within pairs for 8 cells
      int w = (b - NB_SURR)*8 + wl;
      int cnt = 0;
      if (lane < 8) {
        int wc = (b - NB_SURR)*8 + lane;
        cnt = (wc < NC) ? g_wkept[wc] : 0;
      }
      int pre = cnt;
      #pragma unroll
      for (int o = 1; o < 8; o <<= 1) {
        int y = __shfl_up_sync(FULL, pre, o);
        if (lane >= o) pre += y;
      }
      int excl = __shfl_sync(FULL, pre - cnt, wl);
      int n    = __shfl_sync(FULL, cnt, wl);
      if (w >= NC) return;
      int off = blockbase + excl;
      int s = w * CAP_C;
      const float4* scr = &g_scrW[(size_t)w * CAP_W];
      for (int k = lane; k < n; k += 32) {
        float4 v = scr[k];
        int ij = __float_as_int(v.x);
        float fa = (float)__float_as_int(g_sp4[s + (ij & 0xff)].w);
        float fb = (float)__float_as_int(g_sp4[s + (ij >> 8)].w);
        emit_one(out, off + k, fa, fb, v.y, v.z, v.w);
      }
    }
  } else {
    // tail: zero [totalAll, MP) of all 7 streams + re-zero g_cnt for next replay
    int tb = b - NB;                       // 0..NB_TAIL-1
    int zi = tb*blockDim.x + threadIdx.x;
    if (zi < NC) g_cnt[zi] = 0;
    __shared__ int sh_total;
    if (wl == 0) {
      int tot = 0;
      for (int q = lane; q < NCB; q += 32) tot += g_csum[q];
      tot = warp_sum32(tot);
      if (lane == 0) sh_total = tot;
    }
    __syncthreads();
    int total = sh_total;
    int stride = NB_TAIL * blockDim.x;
    for (int i = total + tb*blockDim.x + threadIdx.x; i < MP; i += stride) {
      out[i]        = 0.f;
      out[MP + i]   = 0.f;
      out[2*MP + i] = 0.f;
      out[3*MP + 3*i + 0] = 0.f;
      out[3*MP + 3*i + 1] = 0.f;
      out[3*MP + 3*i + 2] = 0.f;
      out[6*MP + i] = 0.f;
    }
  }
}

// ---------------- launch ----------------
extern "C" void kernel_launch(void* const* d_in, const int* in_sizes, int n_in,
                              void* d_out, int out_size) {
  const float* coords = nullptr;
  for (int i = 0; i < n_in; i++)
    if (in_sizes[i] == 3*NA) coords = (const float*)d_in[i];
  float* out = (float*)d_out;

  k_assign  <<<(NA + 255)/256, 256>>>(coords);    // cells + staging (+csum reset)
  k_sortcell<<<NB_WITH, 256>>>();                 // per-cell id sort -> g_sp4
  k_pairs   <<<NB, 256>>>(coords);                // surround + within, staged + totals
  k_emit    <<<NB + NB_TAIL, 256>>>(out);         // decentralized offsets + emit + tail
}